// round 3
// baseline (speedup 1.0000x reference)
#include <cuda_runtime.h>
#include <math.h>

// GPT-2 124M forward, fp32 baseline.
// Model constants
#define TT   1024
#define DD   768
#define NH   12
#define HDIM 64
#define NB   4
#define MR   (NB*TT)      // 4096 rows
#define VV   50257
#define NL   12

// ---------------------------------------------------------------------------
// Scratch (static device globals: no allocations allowed)
// ---------------------------------------------------------------------------
__device__ float g_x  [MR * DD];        // residual stream
__device__ float g_h  [MR * DD];        // layernorm output
__device__ float g_qkv[MR * 3 * DD];    // qkv
__device__ float g_att[MR * DD];        // attention output
__device__ float g_fc [MR * 4 * DD];    // mlp hidden

// ---------------------------------------------------------------------------
// Embedding: x = wte[ids] + wpe[t]
// ---------------------------------------------------------------------------
__global__ void embed_kernel(const int* __restrict__ ids,
                             const float* __restrict__ wte,
                             const float* __restrict__ wpe,
                             float* __restrict__ x)
{
    int r = blockIdx.x;            // 0..4095
    int tid = threadIdx.x;         // 0..191 (192 float4 per row)
    int id = ids[r];
    int t  = r & (TT - 1);
    float4 a = *(const float4*)(wte + (size_t)id * DD + tid * 4);
    float4 p = *(const float4*)(wpe + (size_t)t  * DD + tid * 4);
    float4 o;
    o.x = a.x + p.x; o.y = a.y + p.y; o.z = a.z + p.z; o.w = a.w + p.w;
    *(float4*)(x + (size_t)r * DD + tid * 4) = o;
}

// ---------------------------------------------------------------------------
// LayerNorm: one block (256 threads) per row of 768
// ---------------------------------------------------------------------------
__global__ __launch_bounds__(256)
void ln_kernel(const float* __restrict__ in, float* __restrict__ out,
               const float* __restrict__ gamma, const float* __restrict__ beta)
{
    __shared__ float red[8];
    __shared__ float bc;
    int r = blockIdx.x, tid = threadIdx.x;
    const float* row = in + (size_t)r * DD;
    float v0 = row[tid], v1 = row[tid + 256], v2 = row[tid + 512];

    float s = v0 + v1 + v2;
    int lane = tid & 31, wid = tid >> 5;
    #pragma unroll
    for (int o = 16; o > 0; o >>= 1) s += __shfl_xor_sync(0xffffffffu, s, o);
    if (lane == 0) red[wid] = s;
    __syncthreads();
    if (tid == 0) { float t = 0.f; for (int i = 0; i < 8; i++) t += red[i]; bc = t; }
    __syncthreads();
    float mu = bc * (1.0f / 768.0f);

    float d0 = v0 - mu, d1 = v1 - mu, d2 = v2 - mu;
    float sq = d0 * d0 + d1 * d1 + d2 * d2;
    #pragma unroll
    for (int o = 16; o > 0; o >>= 1) sq += __shfl_xor_sync(0xffffffffu, sq, o);
    __syncthreads();
    if (lane == 0) red[wid] = sq;
    __syncthreads();
    if (tid == 0) { float t = 0.f; for (int i = 0; i < 8; i++) t += red[i]; bc = t; }
    __syncthreads();
    float rstd = rsqrtf(bc * (1.0f / 768.0f) + 1e-5f);

    float* orow = out + (size_t)r * DD;
    orow[tid]       = d0 * rstd * gamma[tid]       + beta[tid];
    orow[tid + 256] = d1 * rstd * gamma[tid + 256] + beta[tid + 256];
    orow[tid + 512] = d2 * rstd * gamma[tid + 512] + beta[tid + 512];
}

// ---------------------------------------------------------------------------
// GEMM: C = epilogue(A[M,K] @ B[K,N] (+ bias) (+ residual) (gelu))
// TRANSB: B given as [N,K] row-major (logits: wte^T)
// BM=BN=128, BK=16, 256 threads, 8x8 per thread, double-buffered smem.
// ---------------------------------------------------------------------------
#define EPI_NONE      0
#define EPI_BIAS      1
#define EPI_BIAS_GELU 2
#define EPI_BIAS_RES  3

__device__ __forceinline__ float gelu_f(float x)
{
    const float c = 0.7978845608028654f;
    float inner = c * (x + 0.044715f * x * x * x);
    return 0.5f * x * (1.0f + tanhf(inner));
}

template<int EPI, bool TRANSB>
__global__ __launch_bounds__(256)
void sgemm_kernel(const float* __restrict__ A, const float* __restrict__ Bm,
                  const float* __restrict__ bias, const float* __restrict__ res,
                  float* __restrict__ C, int M, int N, int K)
{
    const int BM = 128, BN = 128, BK = 16;
    __shared__ float As[2][BK][BM];
    __shared__ float Bs[2][BK][BN];

    int tid = threadIdx.x;
    int m0 = blockIdx.x * BM, n0 = blockIdx.y * BN;
    int tx = tid & 15, ty = tid >> 4;

    float acc[8][8];
    #pragma unroll
    for (int i = 0; i < 8; i++)
        #pragma unroll
        for (int j = 0; j < 8; j++) acc[i][j] = 0.0f;

    auto fetch = [&](int k0, float4 (&ra)[2], float4 (&rb)[2]) {
        #pragma unroll
        for (int s = 0; s < 2; s++) {
            int lin = tid + s * 256;
            {
                int row = lin >> 2, c4 = lin & 3;
                ra[s] = *(const float4*)(A + (size_t)(m0 + row) * K + k0 + c4 * 4);
            }
            if (!TRANSB) {
                int kk = lin >> 5, n4 = lin & 31;
                rb[s] = *(const float4*)(Bm + (size_t)(k0 + kk) * N + n0 + n4 * 4);
            } else {
                int nn = lin >> 2, c4 = lin & 3;
                if (n0 + nn < N)
                    rb[s] = *(const float4*)(Bm + (size_t)(n0 + nn) * K + k0 + c4 * 4);
                else
                    rb[s] = make_float4(0.f, 0.f, 0.f, 0.f);
            }
        }
    };
    auto store = [&](int buf, const float4 (&ra)[2], const float4 (&rb)[2]) {
        #pragma unroll
        for (int s = 0; s < 2; s++) {
            int lin = tid + s * 256;
            int row = lin >> 2, c4 = lin & 3;
            As[buf][c4 * 4 + 0][row] = ra[s].x;
            As[buf][c4 * 4 + 1][row] = ra[s].y;
            As[buf][c4 * 4 + 2][row] = ra[s].z;
            As[buf][c4 * 4 + 3][row] = ra[s].w;
            if (!TRANSB) {
                int kk = lin >> 5, n4 = lin & 31;
                *(float4*)&Bs[buf][kk][n4 * 4] = rb[s];
            } else {
                int nn = lin >> 2;
                Bs[buf][c4 * 4 + 0][nn] = rb[s].x;
                Bs[buf][c4 * 4 + 1][nn] = rb[s].y;
                Bs[buf][c4 * 4 + 2][nn] = rb[s].z;
                Bs[buf][c4 * 4 + 3][nn] = rb[s].w;
            }
        }
    };

    float4 ra[2], rb[2];
    fetch(0, ra, rb);
    store(0, ra, rb);
    __syncthreads();

    int nt = K / BK;
    for (int t = 0; t < nt; t++) {
        int cur = t & 1;
        bool has = (t + 1) < nt;
        if (has) fetch((t + 1) * BK, ra, rb);

        #pragma unroll
        for (int k = 0; k < BK; k++) {
            float a[8], b[8];
            *(float4*)&a[0] = *(const float4*)&As[cur][k][ty * 8];
            *(float4*)&a[4] = *(const float4*)&As[cur][k][ty * 8 + 4];
            *(float4*)&b[0] = *(const float4*)&Bs[cur][k][tx * 8];
            *(float4*)&b[4] = *(const float4*)&Bs[cur][k][tx * 8 + 4];
            #pragma unroll
            for (int i = 0; i < 8; i++)
                #pragma unroll
                for (int j = 0; j < 8; j++)
                    acc[i][j] += a[i] * b[j];
        }

        if (has) store(cur ^ 1, ra, rb);
        __syncthreads();
    }

    // epilogue
    #pragma unroll
    for (int i = 0; i < 8; i++) {
        int gm = m0 + ty * 8 + i;
        float* crow = C + (size_t)gm * N;
        const float* rrow = (EPI == EPI_BIAS_RES) ? (res + (size_t)gm * N) : nullptr;
        #pragma unroll
        for (int j = 0; j < 8; j++) {
            int gn = n0 + tx * 8 + j;
            if (TRANSB && gn >= N) continue;
            float v = acc[i][j];
            if (EPI == EPI_BIAS || EPI == EPI_BIAS_GELU || EPI == EPI_BIAS_RES)
                v += bias[gn];
            if (EPI == EPI_BIAS_GELU) v = gelu_f(v);
            if (EPI == EPI_BIAS_RES)  v += rrow[gn];
            crow[gn] = v;
        }
    }
}

// ---------------------------------------------------------------------------
// Attention: one block per (q-tile of 64, head, batch). 64 threads; each
// thread owns one q row (q and o in registers), K/V tiles staged in smem,
// online softmax, causal.
// ---------------------------------------------------------------------------
__global__ __launch_bounds__(64)
void attn_kernel(const float* __restrict__ qkv, float* __restrict__ outp)
{
    __shared__ float Ks[64][64];
    __shared__ float Vs[64][64];
    __shared__ float Ss[64][64];   // Ss[j][t]: per-thread score column (bank-clean)

    int qt = blockIdx.x, h = blockIdx.y, b = blockIdx.z;
    int t = threadIdx.x;
    int qrow = qt * 64 + t;
    const float scale = 0.125f;    // 1/sqrt(64)

    const float* qp = qkv + ((size_t)(b * TT + qrow)) * (3 * DD) + h * HDIM;
    float q[64];
    #pragma unroll
    for (int d4 = 0; d4 < 16; d4++) {
        float4 v = *(const float4*)(qp + d4 * 4);
        q[d4 * 4 + 0] = v.x * scale;
        q[d4 * 4 + 1] = v.y * scale;
        q[d4 * 4 + 2] = v.z * scale;
        q[d4 * 4 + 3] = v.w * scale;
    }
    float o[64];
    #pragma unroll
    for (int d = 0; d < 64; d++) o[d] = 0.0f;
    float m = -3.0e38f, l = 0.0f;

    for (int kt = 0; kt <= qt; kt++) {
        const float* kp = qkv + ((size_t)(b * TT + kt * 64 + t)) * (3 * DD) + DD + h * HDIM;
        #pragma unroll
        for (int d4 = 0; d4 < 16; d4++) {
            *(float4*)&Ks[t][d4 * 4] = *(const float4*)(kp + d4 * 4);
            *(float4*)&Vs[t][d4 * 4] = *(const float4*)(kp + DD + d4 * 4);
        }
        __syncthreads();

        int jmax = (kt == qt) ? (t + 1) : 64;
        float tm = -3.0e38f;
        for (int j = 0; j < jmax; j++) {
            float s = 0.0f;
            #pragma unroll
            for (int d = 0; d < 64; d++) s += q[d] * Ks[j][d];
            Ss[j][t] = s;
            tm = fmaxf(tm, s);
        }
        float mnew = fmaxf(m, tm);
        float corr = __expf(m - mnew);
        l *= corr;
        #pragma unroll
        for (int d = 0; d < 64; d++) o[d] *= corr;
        for (int j = 0; j < jmax; j++) {
            float p = __expf(Ss[j][t] - mnew);
            l += p;
            #pragma unroll
            for (int d = 0; d < 64; d++) o[d] += p * Vs[j][d];
        }
        m = mnew;
        __syncthreads();
    }

    float inv = 1.0f / l;
    float* op = outp + ((size_t)(b * TT + qrow)) * DD + h * HDIM;
    #pragma unroll
    for (int d4 = 0; d4 < 16; d4++) {
        float4 v;
        v.x = o[d4 * 4 + 0] * inv;
        v.y = o[d4 * 4 + 1] * inv;
        v.z = o[d4 * 4 + 2] * inv;
        v.w = o[d4 * 4 + 3] * inv;
        *(float4*)(op + d4 * 4) = v;
    }
}

// ---------------------------------------------------------------------------
// Host launcher
// ---------------------------------------------------------------------------
extern "C" void kernel_launch(void* const* d_in, const int* in_sizes, int n_in,
                              void* d_out, int out_size)
{
    (void)in_sizes; (void)n_in; (void)out_size;
    const int*   ids    = (const int*)  d_in[0];
    const float* wte    = (const float*)d_in[1];
    const float* wpe    = (const float*)d_in[2];
    const float* ln1g   = (const float*)d_in[3];
    const float* ln1b   = (const float*)d_in[4];
    const float* wattn  = (const float*)d_in[5];
    const float* battn  = (const float*)d_in[6];
    const float* wproj  = (const float*)d_in[7];
    const float* bproj  = (const float*)d_in[8];
    const float* ln2g   = (const float*)d_in[9];
    const float* ln2b   = (const float*)d_in[10];
    const float* wfc    = (const float*)d_in[11];
    const float* bfc    = (const float*)d_in[12];
    const float* wmproj = (const float*)d_in[13];
    const float* bmproj = (const float*)d_in[14];
    const float* lnfg   = (const float*)d_in[15];
    const float* lnfb   = (const float*)d_in[16];
    float* out = (float*)d_out;

    float *px, *ph, *pqkv, *patt, *pfc;
    cudaGetSymbolAddress((void**)&px,   g_x);
    cudaGetSymbolAddress((void**)&ph,   g_h);
    cudaGetSymbolAddress((void**)&pqkv, g_qkv);
    cudaGetSymbolAddress((void**)&patt, g_att);
    cudaGetSymbolAddress((void**)&pfc,  g_fc);

    embed_kernel<<<MR, 192>>>(ids, wte, wpe, px);

    for (int l = 0; l < NL; l++) {
        ln_kernel<<<MR, 256>>>(px, ph, ln1g + (size_t)l * DD, ln1b + (size_t)l * DD);

        dim3 gqkv(MR / 128, (3 * DD) / 128);   // 32 x 18
        sgemm_kernel<EPI_BIAS, false><<<gqkv, 256>>>(
            ph, wattn + (size_t)l * DD * 3 * DD, battn + (size_t)l * 3 * DD,
            nullptr, pqkv, MR, 3 * DD, DD);

        dim3 gatt(TT / 64, NH, NB);            // 16 x 12 x 4
        attn_kernel<<<gatt, 64>>>(pqkv, patt);

        dim3 gproj(MR / 128, DD / 128);        // 32 x 6
        sgemm_kernel<EPI_BIAS_RES, false><<<gproj, 256>>>(
            patt, wproj + (size_t)l * DD * DD, bproj + (size_t)l * DD,
            px, px, MR, DD, DD);

        ln_kernel<<<MR, 256>>>(px, ph, ln2g + (size_t)l * DD, ln2b + (size_t)l * DD);

        dim3 gfc(MR / 128, (4 * DD) / 128);    // 32 x 24
        sgemm_kernel<EPI_BIAS_GELU, false><<<gfc, 256>>>(
            ph, wfc + (size_t)l * DD * 4 * DD, bfc + (size_t)l * 4 * DD,
            nullptr, pfc, MR, 4 * DD, DD);

        dim3 gmp(MR / 128, DD / 128);          // 32 x 6
        sgemm_kernel<EPI_BIAS_RES, false><<<gmp, 256>>>(
            pfc, wmproj + (size_t)l * 4 * DD * DD, bmproj + (size_t)l * DD,
            px, px, MR, DD, 4 * DD);
    }

    ln_kernel<<<MR, 256>>>(px, ph, lnfg, lnfb);

    dim3 glog(MR / 128, (VV + 127) / 128);     // 32 x 393, M fastest for wte L2 reuse
    sgemm_kernel<EPI_NONE, true><<<glog, 256>>>(
        ph, wte, nullptr, nullptr, out, MR, VV, DD);
}

// round 4
// speedup vs baseline: 1.0019x; 1.0019x over previous
#include <cuda_runtime.h>
#include <math.h>

// GPT-2 124M forward, fp32 baseline.
// Model constants
#define TT   1024
#define DD   768
#define NH   12
#define HDIM 64
#define NB   4
#define MR   (NB*TT)      // 4096 rows
#define VV   50257
#define NL   12

// ---------------------------------------------------------------------------
// Scratch (static device globals: no allocations allowed)
// ---------------------------------------------------------------------------
__device__ float g_x  [MR * DD];        // residual stream
__device__ float g_h  [MR * DD];        // layernorm output
__device__ float g_qkv[MR * 3 * DD];    // qkv
__device__ float g_att[MR * DD];        // attention output
__device__ float g_fc [MR * 4 * DD];    // mlp hidden

// ---------------------------------------------------------------------------
// Embedding: x = wte[ids] + wpe[t]
// ---------------------------------------------------------------------------
__global__ void embed_kernel(const int* __restrict__ ids,
                             const float* __restrict__ wte,
                             const float* __restrict__ wpe,
                             float* __restrict__ x)
{
    int r = blockIdx.x;            // 0..4095
    int tid = threadIdx.x;         // 0..191 (192 float4 per row)
    int id = ids[r];
    int t  = r & (TT - 1);
    float4 a = *(const float4*)(wte + (size_t)id * DD + tid * 4);
    float4 p = *(const float4*)(wpe + (size_t)t  * DD + tid * 4);
    float4 o;
    o.x = a.x + p.x; o.y = a.y + p.y; o.z = a.z + p.z; o.w = a.w + p.w;
    *(float4*)(x + (size_t)r * DD + tid * 4) = o;
}

// ---------------------------------------------------------------------------
// LayerNorm: one block (256 threads) per row of 768
// ---------------------------------------------------------------------------
__global__ __launch_bounds__(256)
void ln_kernel(const float* __restrict__ in, float* __restrict__ out,
               const float* __restrict__ gamma, const float* __restrict__ beta)
{
    __shared__ float red[8];
    __shared__ float bc;
    int r = blockIdx.x, tid = threadIdx.x;
    const float* row = in + (size_t)r * DD;
    float v0 = row[tid], v1 = row[tid + 256], v2 = row[tid + 512];

    float s = v0 + v1 + v2;
    int lane = tid & 31, wid = tid >> 5;
    #pragma unroll
    for (int o = 16; o > 0; o >>= 1) s += __shfl_xor_sync(0xffffffffu, s, o);
    if (lane == 0) red[wid] = s;
    __syncthreads();
    if (tid == 0) { float t = 0.f; for (int i = 0; i < 8; i++) t += red[i]; bc = t; }
    __syncthreads();
    float mu = bc * (1.0f / 768.0f);

    float d0 = v0 - mu, d1 = v1 - mu, d2 = v2 - mu;
    float sq = d0 * d0 + d1 * d1 + d2 * d2;
    #pragma unroll
    for (int o = 16; o > 0; o >>= 1) sq += __shfl_xor_sync(0xffffffffu, sq, o);
    __syncthreads();
    if (lane == 0) red[wid] = sq;
    __syncthreads();
    if (tid == 0) { float t = 0.f; for (int i = 0; i < 8; i++) t += red[i]; bc = t; }
    __syncthreads();
    float rstd = rsqrtf(bc * (1.0f / 768.0f) + 1e-5f);

    float* orow = out + (size_t)r * DD;
    orow[tid]       = d0 * rstd * gamma[tid]       + beta[tid];
    orow[tid + 256] = d1 * rstd * gamma[tid + 256] + beta[tid + 256];
    orow[tid + 512] = d2 * rstd * gamma[tid + 512] + beta[tid + 512];
}

// ---------------------------------------------------------------------------
// GEMM: C = epilogue(A[M,K] @ B[K,N] (+ bias) (+ residual) (gelu))
// TRANSB: B given as [N,K] row-major (logits: wte^T)
// BM=BN=128, BK=16, 256 threads, 8x8 per thread, double-buffered smem.
// ---------------------------------------------------------------------------
#define EPI_NONE      0
#define EPI_BIAS      1
#define EPI_BIAS_GELU 2
#define EPI_BIAS_RES  3

__device__ __forceinline__ float gelu_f(float x)
{
    const float c = 0.7978845608028654f;
    float inner = c * (x + 0.044715f * x * x * x);
    return 0.5f * x * (1.0f + tanhf(inner));
}

template<int EPI, bool TRANSB>
__global__ __launch_bounds__(256)
void sgemm_kernel(const float* __restrict__ A, const float* __restrict__ Bm,
                  const float* __restrict__ bias, const float* __restrict__ res,
                  float* __restrict__ C, int M, int N, int K)
{
    const int BM = 128, BN = 128, BK = 16;
    __shared__ float As[2][BK][BM];
    __shared__ float Bs[2][BK][BN];

    int tid = threadIdx.x;
    int m0 = blockIdx.x * BM, n0 = blockIdx.y * BN;
    int tx = tid & 15, ty = tid >> 4;

    float acc[8][8];
    #pragma unroll
    for (int i = 0; i < 8; i++)
        #pragma unroll
        for (int j = 0; j < 8; j++) acc[i][j] = 0.0f;

    auto fetch = [&](int k0, float4 (&ra)[2], float4 (&rb)[2]) {
        #pragma unroll
        for (int s = 0; s < 2; s++) {
            int lin = tid + s * 256;
            {
                int row = lin >> 2, c4 = lin & 3;
                ra[s] = *(const float4*)(A + (size_t)(m0 + row) * K + k0 + c4 * 4);
            }
            if (!TRANSB) {
                int kk = lin >> 5, n4 = lin & 31;
                rb[s] = *(const float4*)(Bm + (size_t)(k0 + kk) * N + n0 + n4 * 4);
            } else {
                int nn = lin >> 2, c4 = lin & 3;
                if (n0 + nn < N)
                    rb[s] = *(const float4*)(Bm + (size_t)(n0 + nn) * K + k0 + c4 * 4);
                else
                    rb[s] = make_float4(0.f, 0.f, 0.f, 0.f);
            }
        }
    };
    auto store = [&](int buf, const float4 (&ra)[2], const float4 (&rb)[2]) {
        #pragma unroll
        for (int s = 0; s < 2; s++) {
            int lin = tid + s * 256;
            int row = lin >> 2, c4 = lin & 3;
            As[buf][c4 * 4 + 0][row] = ra[s].x;
            As[buf][c4 * 4 + 1][row] = ra[s].y;
            As[buf][c4 * 4 + 2][row] = ra[s].z;
            As[buf][c4 * 4 + 3][row] = ra[s].w;
            if (!TRANSB) {
                int kk = lin >> 5, n4 = lin & 31;
                *(float4*)&Bs[buf][kk][n4 * 4] = rb[s];
            } else {
                int nn = lin >> 2;
                Bs[buf][c4 * 4 + 0][nn] = rb[s].x;
                Bs[buf][c4 * 4 + 1][nn] = rb[s].y;
                Bs[buf][c4 * 4 + 2][nn] = rb[s].z;
                Bs[buf][c4 * 4 + 3][nn] = rb[s].w;
            }
        }
    };

    float4 ra[2], rb[2];
    fetch(0, ra, rb);
    store(0, ra, rb);
    __syncthreads();

    int nt = K / BK;
    for (int t = 0; t < nt; t++) {
        int cur = t & 1;
        bool has = (t + 1) < nt;
        if (has) fetch((t + 1) * BK, ra, rb);

        #pragma unroll
        for (int k = 0; k < BK; k++) {
            float a[8], b[8];
            *(float4*)&a[0] = *(const float4*)&As[cur][k][ty * 8];
            *(float4*)&a[4] = *(const float4*)&As[cur][k][ty * 8 + 4];
            *(float4*)&b[0] = *(const float4*)&Bs[cur][k][tx * 8];
            *(float4*)&b[4] = *(const float4*)&Bs[cur][k][tx * 8 + 4];
            #pragma unroll
            for (int i = 0; i < 8; i++)
                #pragma unroll
                for (int j = 0; j < 8; j++)
                    acc[i][j] += a[i] * b[j];
        }

        if (has) store(cur ^ 1, ra, rb);
        __syncthreads();
    }

    // epilogue
    #pragma unroll
    for (int i = 0; i < 8; i++) {
        int gm = m0 + ty * 8 + i;
        float* crow = C + (size_t)gm * N;
        const float* rrow = (EPI == EPI_BIAS_RES) ? (res + (size_t)gm * N) : nullptr;
        #pragma unroll
        for (int j = 0; j < 8; j++) {
            int gn = n0 + tx * 8 + j;
            if (TRANSB && gn >= N) continue;
            float v = acc[i][j];
            if (EPI == EPI_BIAS || EPI == EPI_BIAS_GELU || EPI == EPI_BIAS_RES)
                v += bias[gn];
            if (EPI == EPI_BIAS_GELU) v = gelu_f(v);
            if (EPI == EPI_BIAS_RES)  v += rrow[gn];
            crow[gn] = v;
        }
    }
}

// ---------------------------------------------------------------------------
// Attention: one block per (q-tile of 64, head, batch). 64 threads; each
// thread owns one q row (q and o in registers), K/V tiles staged in smem,
// online softmax, causal.
// ---------------------------------------------------------------------------
__global__ __launch_bounds__(64)
void attn_kernel(const float* __restrict__ qkv, float* __restrict__ outp)
{
    __shared__ float Ks[64][64];
    __shared__ float Vs[64][64];
    __shared__ float Ss[64][64];   // Ss[j][t]: per-thread score column (bank-clean)

    int qt = blockIdx.x, h = blockIdx.y, b = blockIdx.z;
    int t = threadIdx.x;
    int qrow = qt * 64 + t;
    const float scale = 0.125f;    // 1/sqrt(64)

    const float* qp = qkv + ((size_t)(b * TT + qrow)) * (3 * DD) + h * HDIM;
    float q[64];
    #pragma unroll
    for (int d4 = 0; d4 < 16; d4++) {
        float4 v = *(const float4*)(qp + d4 * 4);
        q[d4 * 4 + 0] = v.x * scale;
        q[d4 * 4 + 1] = v.y * scale;
        q[d4 * 4 + 2] = v.z * scale;
        q[d4 * 4 + 3] = v.w * scale;
    }
    float o[64];
    #pragma unroll
    for (int d = 0; d < 64; d++) o[d] = 0.0f;
    float m = -3.0e38f, l = 0.0f;

    for (int kt = 0; kt <= qt; kt++) {
        const float* kp = qkv + ((size_t)(b * TT + kt * 64 + t)) * (3 * DD) + DD + h * HDIM;
        #pragma unroll
        for (int d4 = 0; d4 < 16; d4++) {
            *(float4*)&Ks[t][d4 * 4] = *(const float4*)(kp + d4 * 4);
            *(float4*)&Vs[t][d4 * 4] = *(const float4*)(kp + DD + d4 * 4);
        }
        __syncthreads();

        int jmax = (kt == qt) ? (t + 1) : 64;
        float tm = -3.0e38f;
        for (int j = 0; j < jmax; j++) {
            float s = 0.0f;
            #pragma unroll
            for (int d = 0; d < 64; d++) s += q[d] * Ks[j][d];
            Ss[j][t] = s;
            tm = fmaxf(tm, s);
        }
        float mnew = fmaxf(m, tm);
        float corr = __expf(m - mnew);
        l *= corr;
        #pragma unroll
        for (int d = 0; d < 64; d++) o[d] *= corr;
        for (int j = 0; j < jmax; j++) {
            float p = __expf(Ss[j][t] - mnew);
            l += p;
            #pragma unroll
            for (int d = 0; d < 64; d++) o[d] += p * Vs[j][d];
        }
        m = mnew;
        __syncthreads();
    }

    float inv = 1.0f / l;
    float* op = outp + ((size_t)(b * TT + qrow)) * DD + h * HDIM;
    #pragma unroll
    for (int d4 = 0; d4 < 16; d4++) {
        float4 v;
        v.x = o[d4 * 4 + 0] * inv;
        v.y = o[d4 * 4 + 1] * inv;
        v.z = o[d4 * 4 + 2] * inv;
        v.w = o[d4 * 4 + 3] * inv;
        *(float4*)(op + d4 * 4) = v;
    }
}

// ---------------------------------------------------------------------------
// Host launcher
// ---------------------------------------------------------------------------
extern "C" void kernel_launch(void* const* d_in, const int* in_sizes, int n_in,
                              void* d_out, int out_size)
{
    (void)in_sizes; (void)n_in; (void)out_size;
    const int*   ids    = (const int*)  d_in[0];
    const float* wte    = (const float*)d_in[1];
    const float* wpe    = (const float*)d_in[2];
    const float* ln1g   = (const float*)d_in[3];
    const float* ln1b   = (const float*)d_in[4];
    const float* wattn  = (const float*)d_in[5];
    const float* battn  = (const float*)d_in[6];
    const float* wproj  = (const float*)d_in[7];
    const float* bproj  = (const float*)d_in[8];
    const float* ln2g   = (const float*)d_in[9];
    const float* ln2b   = (const float*)d_in[10];
    const float* wfc    = (const float*)d_in[11];
    const float* bfc    = (const float*)d_in[12];
    const float* wmproj = (const float*)d_in[13];
    const float* bmproj = (const float*)d_in[14];
    const float* lnfg   = (const float*)d_in[15];
    const float* lnfb   = (const float*)d_in[16];
    float* out = (float*)d_out;

    float *px, *ph, *pqkv, *patt, *pfc;
    cudaGetSymbolAddress((void**)&px,   g_x);
    cudaGetSymbolAddress((void**)&ph,   g_h);
    cudaGetSymbolAddress((void**)&pqkv, g_qkv);
    cudaGetSymbolAddress((void**)&patt, g_att);
    cudaGetSymbolAddress((void**)&pfc,  g_fc);

    embed_kernel<<<MR, 192>>>(ids, wte, wpe, px);

    for (int l = 0; l < NL; l++) {
        ln_kernel<<<MR, 256>>>(px, ph, ln1g + (size_t)l * DD, ln1b + (size_t)l * DD);

        dim3 gqkv(MR / 128, (3 * DD) / 128);   // 32 x 18
        sgemm_kernel<EPI_BIAS, false><<<gqkv, 256>>>(
            ph, wattn + (size_t)l * DD * 3 * DD, battn + (size_t)l * 3 * DD,
            nullptr, pqkv, MR, 3 * DD, DD);

        dim3 gatt(TT / 64, NH, NB);            // 16 x 12 x 4
        attn_kernel<<<gatt, 64>>>(pqkv, patt);

        dim3 gproj(MR / 128, DD / 128);        // 32 x 6
        sgemm_kernel<EPI_BIAS_RES, false><<<gproj, 256>>>(
            patt, wproj + (size_t)l * DD * DD, bproj + (size_t)l * DD,
            px, px, MR, DD, DD);

        ln_kernel<<<MR, 256>>>(px, ph, ln2g + (size_t)l * DD, ln2b + (size_t)l * DD);

        dim3 gfc(MR / 128, (4 * DD) / 128);    // 32 x 24
        sgemm_kernel<EPI_BIAS_GELU, false><<<gfc, 256>>>(
            ph, wfc + (size_t)l * DD * 4 * DD, bfc + (size_t)l * 4 * DD,
            nullptr, pfc, MR, 4 * DD, DD);

        dim3 gmp(MR / 128, DD / 128);          // 32 x 6
        sgemm_kernel<EPI_BIAS_RES, false><<<gmp, 256>>>(
            pfc, wmproj + (size_t)l * 4 * DD * DD, bmproj + (size_t)l * DD,
            px, px, MR, DD, 4 * DD);
    }

    ln_kernel<<<MR, 256>>>(px, ph, lnfg, lnfb);

    dim3 glog(MR / 128, (VV + 127) / 128);     // 32 x 393, M fastest for wte L2 reuse
    sgemm_kernel<EPI_NONE, true><<<glog, 256>>>(
        ph, wte, nullptr, nullptr, out, MR, VV, DD);
}